// round 5
// baseline (speedup 1.0000x reference)
#include <cuda_runtime.h>
#include <cuda_bf16.h>
#include <cstdint>

// Problem shape
#define B_DIM 64
#define T_DIM 512
#define D_DIM 1024
#define U_DIM 128
#define M_TOTAL (B_DIM * T_DIM)        // 32768
#define M_TILE  128
#define K_CHUNK 32
#define NUM_CHUNKS (D_DIM / K_CHUNK)   // 32
#define NUM_CTAS (M_TOTAL / M_TILE)    // 256
#define THREADS 256

// SMEM layout
#define OFF_BIAS  0
#define OFF_LB    512
#define OFF_RB    1024
#define OFF_TILES 1536
#define TILE_BYTES 8192                 // 128 rows x 64B (32 bf16)
#define STAGE_BYTES (4 * TILE_BYTES)    // Ahi, Alo, Bhi, Blo
#define T_AHI 0
#define T_ALO TILE_BYTES
#define T_BHI (2 * TILE_BYTES)
#define T_BLO (3 * TILE_BYTES)
#define SMEM_TOTAL (OFF_TILES + 2 * STAGE_BYTES)   // 67072

// Pre-split B operand (kernel^T), K-major [U][D], bf16 hi/lo
__device__ __align__(16) __nv_bfloat16 g_Bhi[U_DIM * D_DIM];
__device__ __align__(16) __nv_bfloat16 g_Blo[U_DIM * D_DIM];

// ---------------- helpers ----------------
static __device__ __forceinline__ uint32_t smem_u32(const void* p) {
    uint32_t a;
    asm("{ .reg .u64 t; cvta.to.shared.u64 t, %1; cvt.u32.u64 %0, t; }" : "=r"(a) : "l"(p));
    return a;
}

// pack two f32 -> bf16x2 (lo in low half, hi in high half), round-to-nearest
static __device__ __forceinline__ uint32_t f2bf2(float lo, float hi) {
    uint32_t r;
    asm("cvt.rn.bf16x2.f32 %0, %1, %2;" : "=r"(r) : "f"(hi), "f"(lo));
    return r;
}

// swizzled byte offset of 16B chunk c (0..3) in row r of a 64B-wide tile
static __device__ __forceinline__ uint32_t swz(uint32_t r, uint32_t c) {
    return r * 64u + ((c ^ ((r >> 1) & 3u)) << 4);
}

#define LDMX4(R, addr) \
    asm volatile("ldmatrix.sync.aligned.m8n8.x4.shared.b16 {%0,%1,%2,%3}, [%4];" \
        : "=r"((R)[0]), "=r"((R)[1]), "=r"((R)[2]), "=r"((R)[3]) : "r"(addr))

#define MMA_BF16(acc, A, B0, B1) \
    asm volatile("mma.sync.aligned.m16n8k16.row.col.f32.bf16.bf16.f32 " \
        "{%0,%1,%2,%3}, {%4,%5,%6,%7}, {%8,%9}, {%0,%1,%2,%3};" \
        : "+f"((acc)[0]), "+f"((acc)[1]), "+f"((acc)[2]), "+f"((acc)[3]) \
        : "r"((A)[0]), "r"((A)[1]), "r"((A)[2]), "r"((A)[3]), "r"(B0), "r"(B1))

// ---------------- Prologue: split kernel[D,U] -> Bhi/Blo [U,D] bf16 ----------------
__global__ void crf_bsplit_kernel(const float* __restrict__ kern) {
    int e = blockIdx.x * blockDim.x + threadIdx.x;   // e = u*D + d
    int u = e >> 10;
    int d = e & (D_DIM - 1);
    float v = kern[d * U_DIM + u];
    __nv_bfloat16 h = __float2bfloat16(v);
    __nv_bfloat16 l = __float2bfloat16(v - __bfloat162float(h));
    g_Bhi[e] = h;
    g_Blo[e] = l;
}

// ---------------- Main fused GEMM + boundary epilogue ----------------
__global__ __launch_bounds__(THREADS, 1) void crf_gemm_kernel(
    const float* __restrict__ x, const int* __restrict__ mask,
    const float* __restrict__ bias, const float* __restrict__ lb,
    const float* __restrict__ rb, float* __restrict__ out)
{
    extern __shared__ char smem[];
    const uint32_t smem_base = smem_u32(smem);
    const int tid = threadIdx.x;
    const int wid = tid >> 5;
    const int lid = tid & 31;
    const int warp_m = (wid & 3) * 32;   // 4 warps along M
    const int warp_n = (wid >> 2) * 64;  // 2 warps along N

    // stage bias / boundary vectors into smem
    if (tid < U_DIM) {
        ((float*)(smem + OFF_BIAS))[tid] = bias[tid];
        ((float*)(smem + OFF_LB))[tid]   = lb[tid];
        ((float*)(smem + OFF_RB))[tid]   = rb[tid];
    }

    // precompute per-lane ldmatrix offsets
    uint32_t a_off[2][2];   // [mb][ks]
    #pragma unroll
    for (int mb = 0; mb < 2; mb++)
        #pragma unroll
        for (int ks = 0; ks < 2; ks++) {
            uint32_t r = warp_m + mb * 16 + (lid & 15);
            uint32_t c = ks * 2 + (lid >> 4);
            a_off[mb][ks] = swz(r, c);
        }
    uint32_t b_off[2][4];   // [ks][g]
    #pragma unroll
    for (int ks = 0; ks < 2; ks++)
        #pragma unroll
        for (int g = 0; g < 4; g++) {
            uint32_t n = warp_n + g * 16 + (lid & 7) + ((lid >> 4) & 1) * 8;
            uint32_t c = ks * 2 + ((lid >> 3) & 1);
            b_off[ks][g] = swz(n, c);
        }

    const float* xblk = x + (size_t)blockIdx.x * (M_TILE * D_DIM);
    const uint4* gbh = reinterpret_cast<const uint4*>(g_Bhi);
    const uint4* gbl = reinterpret_cast<const uint4*>(g_Blo);

    float acc[2][8][4];
    #pragma unroll
    for (int mb = 0; mb < 2; mb++)
        #pragma unroll
        for (int nb = 0; nb < 8; nb++)
            #pragma unroll
            for (int i = 0; i < 4; i++) acc[mb][nb][i] = 0.0f;

    float4 ax[4];
    uint4 bhq[2], blq[2];

    auto LOADREG = [&](int kc) {
        const int k0 = kc * K_CHUNK;
        #pragma unroll
        for (int j = 0; j < 4; j++) {
            int f = tid + THREADS * j;      // float4 index in 128x32 fp32 tile
            int r = f >> 3, c4 = f & 7;     // 8 float4 per row
            ax[j] = *reinterpret_cast<const float4*>(xblk + (size_t)r * D_DIM + k0 + c4 * 4);
        }
        const int kq = k0 >> 3;             // uint4 offset within 1024-col bf16 row
        #pragma unroll
        for (int j = 0; j < 2; j++) {
            int f = tid + THREADS * j;      // uint4 index in 128x32 bf16 tile
            int n = f >> 2, s = f & 3;      // 4 uint4 per 64B row
            int qi = n * (D_DIM / 8) + kq + s;
            bhq[j] = gbh[qi];
            blq[j] = gbl[qi];
        }
    };

    auto STS = [&](int stage) {
        const uint32_t sb = smem_base + OFF_TILES + stage * STAGE_BYTES;
        #pragma unroll
        for (int j = 0; j < 4; j++) {
            int f = tid + THREADS * j;
            int r = f >> 3, c4 = f & 7;
            float4 v = ax[j];
            uint32_t h01 = f2bf2(v.x, v.y);
            uint32_t h23 = f2bf2(v.z, v.w);
            float hx = __uint_as_float(h01 << 16);
            float hy = __uint_as_float(h01 & 0xFFFF0000u);
            float hz = __uint_as_float(h23 << 16);
            float hw = __uint_as_float(h23 & 0xFFFF0000u);
            uint32_t l01 = f2bf2(v.x - hx, v.y - hy);
            uint32_t l23 = f2bf2(v.z - hz, v.w - hw);
            uint32_t addr = swz((uint32_t)r, (uint32_t)(c4 >> 1)) + (c4 & 1) * 8;
            uint64_t hv = ((uint64_t)h23 << 32) | h01;
            uint64_t lv = ((uint64_t)l23 << 32) | l01;
            asm volatile("st.shared.b64 [%0], %1;" :: "r"(sb + T_AHI + addr), "l"(hv) : "memory");
            asm volatile("st.shared.b64 [%0], %1;" :: "r"(sb + T_ALO + addr), "l"(lv) : "memory");
        }
        #pragma unroll
        for (int j = 0; j < 2; j++) {
            int f = tid + THREADS * j;
            int n = f >> 2, s = f & 3;
            uint32_t addr = swz((uint32_t)n, (uint32_t)s);
            asm volatile("st.shared.v4.b32 [%0], {%1,%2,%3,%4};"
                :: "r"(sb + T_BHI + addr),
                   "r"(bhq[j].x), "r"(bhq[j].y), "r"(bhq[j].z), "r"(bhq[j].w) : "memory");
            asm volatile("st.shared.v4.b32 [%0], {%1,%2,%3,%4};"
                :: "r"(sb + T_BLO + addr),
                   "r"(blq[j].x), "r"(blq[j].y), "r"(blq[j].z), "r"(blq[j].w) : "memory");
        }
    };

    LOADREG(0);
    STS(0);
    __syncthreads();

    for (int kc = 0; kc < NUM_CHUNKS; kc++) {
        if (kc + 1 < NUM_CHUNKS) LOADREG(kc + 1);

        const uint32_t sb = smem_base + OFF_TILES + (kc & 1) * STAGE_BYTES;
        const uint32_t sah = sb + T_AHI, sal = sb + T_ALO;
        const uint32_t sbh = sb + T_BHI, sbl = sb + T_BLO;

        #pragma unroll
        for (int ks = 0; ks < 2; ks++) {
            uint32_t ah0[4], ah1[4], al0[4], al1[4];
            LDMX4(ah0, sah + a_off[0][ks]);
            LDMX4(ah1, sah + a_off[1][ks]);
            LDMX4(al0, sal + a_off[0][ks]);
            LDMX4(al1, sal + a_off[1][ks]);
            uint32_t bh[4][4], bl[4][4];
            #pragma unroll
            for (int g = 0; g < 4; g++) {
                LDMX4(bh[g], sbh + b_off[ks][g]);
                LDMX4(bl[g], sbl + b_off[ks][g]);
            }
            #pragma unroll
            for (int g = 0; g < 4; g++) {
                #pragma unroll
                for (int h = 0; h < 2; h++) {
                    const int nb = g * 2 + h;
                    const uint32_t bh0 = bh[g][2 * h], bh1 = bh[g][2 * h + 1];
                    const uint32_t bl0 = bl[g][2 * h], bl1 = bl[g][2 * h + 1];
                    MMA_BF16(acc[0][nb], ah0, bh0, bh1);
                    MMA_BF16(acc[1][nb], ah1, bh0, bh1);
                    MMA_BF16(acc[0][nb], al0, bh0, bh1);
                    MMA_BF16(acc[1][nb], al1, bh0, bh1);
                    MMA_BF16(acc[0][nb], ah0, bl0, bl1);
                    MMA_BF16(acc[1][nb], ah1, bl0, bl1);
                }
            }
        }

        if (kc + 1 < NUM_CHUNKS) {
            STS((kc + 1) & 1);
            __syncthreads();
        }
    }

    // ---- epilogue: bias + mask-gated boundaries, straight from registers ----
    const float* sbias = (const float*)(smem + OFF_BIAS);
    const float* slb   = (const float*)(smem + OFF_LB);
    const float* srb   = (const float*)(smem + OFF_RB);
    const int gid = lid >> 2, tig = lid & 3;

    #pragma unroll
    for (int mb = 0; mb < 2; mb++) {
        #pragma unroll
        for (int p = 0; p < 2; p++) {
            int row = warp_m + mb * 16 + p * 8 + gid;
            int gm = blockIdx.x * M_TILE + row;
            int t = gm & (T_DIM - 1);
            int mc = mask[gm];
            int mp = (t > 0) ? mask[gm - 1] : 0;
            int mn = (t < T_DIM - 1) ? mask[gm + 1] : 0;
            float s = (mc > mp) ? 1.0f : 0.0f;
            float e = (mn > mc) ? 1.0f : 0.0f;
            float* orow = out + (size_t)gm * U_DIM;
            #pragma unroll
            for (int nb = 0; nb < 8; nb++) {
                int c = warp_n + nb * 8 + 2 * tig;
                float2 o;
                o.x = acc[mb][nb][2 * p + 0] + sbias[c + 0] + s * slb[c + 0] + e * srb[c + 0];
                o.y = acc[mb][nb][2 * p + 1] + sbias[c + 1] + s * slb[c + 1] + e * srb[c + 1];
                *reinterpret_cast<float2*>(orow + c) = o;
            }
        }
    }
}

extern "C" void kernel_launch(void* const* d_in, const int* in_sizes, int n_in,
                              void* d_out, int out_size) {
    const float* x    = (const float*)d_in[0];
    const int*   mask = (const int*)d_in[1];
    const float* kern = (const float*)d_in[2];
    const float* bias = (const float*)d_in[3];
    const float* lb   = (const float*)d_in[4];
    const float* rb   = (const float*)d_in[5];
    float* out = (float*)d_out;

    cudaFuncSetAttribute(crf_gemm_kernel,
                         cudaFuncAttributeMaxDynamicSharedMemorySize, SMEM_TOTAL);

    crf_bsplit_kernel<<<(U_DIM * D_DIM) / THREADS, THREADS>>>(kern);
    crf_gemm_kernel<<<NUM_CTAS, THREADS, SMEM_TOTAL>>>(x, mask, bias, lb, rb, out);
}

// round 6
// speedup vs baseline: 1.4402x; 1.4402x over previous
#include <cuda_runtime.h>
#include <cuda_fp16.h>
#include <cstdint>

// Problem shape
#define B_DIM 64
#define T_DIM 512
#define D_DIM 1024
#define U_DIM 128
#define M_TOTAL (B_DIM * T_DIM)        // 32768
#define M_TILE  128
#define K_CHUNK 64
#define NUM_CHUNKS (D_DIM / K_CHUNK)   // 16
#define NUM_CTAS (M_TOTAL / M_TILE)    // 256
#define THREADS 512

// SMEM layout
#define OFF_BIAS  0
#define OFF_LB    512
#define OFF_RB    1024
#define OFF_TILES 1536
#define TILE_BYTES 16384                // 128 rows x 128B (64 fp16)
#define STAGE_BYTES (3 * TILE_BYTES)    // A-hi, A-lo, B-hi
#define T_AH 0
#define T_AL TILE_BYTES
#define T_BH (2 * TILE_BYTES)
#define SMEM_TOTAL (OFF_TILES + 2 * STAGE_BYTES)   // 99840

// Pre-converted B operand (kernel^T), K-major [U][D], fp16
__device__ __align__(16) __half g_Bh[U_DIM * D_DIM];

// ---------------- helpers ----------------
static __device__ __forceinline__ uint32_t smem_u32(const void* p) {
    uint32_t a;
    asm("{ .reg .u64 t; cvta.to.shared.u64 t, %1; cvt.u32.u64 %0, t; }" : "=r"(a) : "l"(p));
    return a;
}
static __device__ __forceinline__ uint32_t h2u(__half2 h) {
    return *reinterpret_cast<uint32_t*>(&h);
}
// swizzled byte offset of 16B chunk c (0..7) in row r of a 128B-wide tile
static __device__ __forceinline__ uint32_t swz(uint32_t r, uint32_t c) {
    return r * 128u + ((c ^ (r & 7u)) << 4);
}

#define LDMX4(R, addr) \
    asm volatile("ldmatrix.sync.aligned.m8n8.x4.shared.b16 {%0,%1,%2,%3}, [%4];" \
        : "=r"((R)[0]), "=r"((R)[1]), "=r"((R)[2]), "=r"((R)[3]) : "r"(addr))

#define MMA_F16(acc, A0, A1, A2, A3, B0, B1) \
    asm volatile("mma.sync.aligned.m16n8k16.row.col.f32.f16.f16.f32 " \
        "{%0,%1,%2,%3}, {%4,%5,%6,%7}, {%8,%9}, {%0,%1,%2,%3};" \
        : "+f"((acc)[0]), "+f"((acc)[1]), "+f"((acc)[2]), "+f"((acc)[3]) \
        : "r"(A0), "r"(A1), "r"(A2), "r"(A3), "r"(B0), "r"(B1))

#define CP_ASYNC16(dst, src) \
    asm volatile("cp.async.cg.shared.global [%0], [%1], 16;" \
                 :: "r"(dst), "l"(src) : "memory")
#define CP_COMMIT() asm volatile("cp.async.commit_group;" ::: "memory")
#define CP_WAIT0()  asm volatile("cp.async.wait_group 0;" ::: "memory")

// ---------------- Prologue: kernel[D,U] -> g_Bh [U,D] fp16 ----------------
__global__ void crf_bprep_kernel(const float* __restrict__ kern) {
    int e = blockIdx.x * blockDim.x + threadIdx.x;   // e = u*D + d
    int u = e >> 10;
    int d = e & (D_DIM - 1);
    g_Bh[e] = __float2half(kern[d * U_DIM + u]);
}

// ---------------- Main fused GEMM + boundary epilogue ----------------
__global__ __launch_bounds__(THREADS, 1) void crf_gemm_kernel(
    const float* __restrict__ x, const int* __restrict__ mask,
    const float* __restrict__ bias, const float* __restrict__ lb,
    const float* __restrict__ rb, float* __restrict__ out)
{
    extern __shared__ char smem[];
    const uint32_t smem_base = smem_u32(smem);
    const int tid = threadIdx.x;
    const int wid = tid >> 5;
    const int lid = tid & 31;
    const int warp_m = (wid & 3) * 32;   // 4 warps along M
    const int warp_n = (wid >> 2) * 32;  // 4 warps along N

    // stage bias / boundary vectors
    if (tid < U_DIM) {
        ((float*)(smem + OFF_BIAS))[tid] = bias[tid];
        ((float*)(smem + OFF_LB))[tid]   = lb[tid];
        ((float*)(smem + OFF_RB))[tid]   = rb[tid];
    }

    // per-lane ldmatrix offsets
    uint32_t a_off[2][4];   // [mb][ks]
    #pragma unroll
    for (int mb = 0; mb < 2; mb++)
        #pragma unroll
        for (int ks = 0; ks < 4; ks++) {
            uint32_t r = warp_m + mb * 16 + (lid & 15);
            uint32_t c = ks * 2 + (lid >> 4);
            a_off[mb][ks] = swz(r, c);
        }
    uint32_t b_off[2][4];   // [g][ks]
    #pragma unroll
    for (int g = 0; g < 2; g++)
        #pragma unroll
        for (int ks = 0; ks < 4; ks++) {
            uint32_t n = warp_n + g * 16 + (lid & 7) + ((lid >> 4) & 1) * 8;
            uint32_t c = ks * 2 + ((lid >> 3) & 1);
            b_off[g][ks] = swz(n, c);
        }

    const float* xblk = x + (size_t)blockIdx.x * (M_TILE * D_DIM);
    const __half* gbh = g_Bh;

    float acc[2][4][4];
    #pragma unroll
    for (int mb = 0; mb < 2; mb++)
        #pragma unroll
        for (int nb = 0; nb < 4; nb++)
            #pragma unroll
            for (int i = 0; i < 4; i++) acc[mb][nb][i] = 0.0f;

    float4 ax[4];

    auto LOADX = [&](int kc) {
        const int k0 = kc * K_CHUNK;
        #pragma unroll
        for (int j = 0; j < 4; j++) {
            int f = tid + THREADS * j;      // float4 index in 128x64 fp32 tile
            int r = f >> 4, c4 = f & 15;    // 16 float4 per row
            ax[j] = *reinterpret_cast<const float4*>(xblk + (size_t)r * D_DIM + k0 + c4 * 4);
        }
    };
    auto CPB = [&](int kc, int stage) {
        const uint32_t sb = smem_base + OFF_TILES + stage * STAGE_BYTES + T_BH;
        const int k0 = kc * K_CHUNK;
        #pragma unroll
        for (int j = 0; j < 2; j++) {
            int f = tid + THREADS * j;      // 16B chunk index in 128x128B tile
            int n = f >> 3, s = f & 7;
            CP_ASYNC16(sb + swz((uint32_t)n, (uint32_t)s),
                       gbh + (size_t)n * D_DIM + k0 + s * 8);
        }
    };
    auto STSA = [&](int stage) {
        const uint32_t sb = smem_base + OFF_TILES + stage * STAGE_BYTES;
        #pragma unroll
        for (int j = 0; j < 4; j++) {
            int f = tid + THREADS * j;
            int r = f >> 4, c4 = f & 15;
            float4 v = ax[j];
            __half2 h01 = __float22half2_rn(make_float2(v.x, v.y));
            __half2 h23 = __float22half2_rn(make_float2(v.z, v.w));
            float2 f01 = __half22float2(h01);
            float2 f23 = __half22float2(h23);
            __half2 l01 = __float22half2_rn(make_float2(v.x - f01.x, v.y - f01.y));
            __half2 l23 = __float22half2_rn(make_float2(v.z - f23.x, v.w - f23.y));
            uint32_t addr = swz((uint32_t)r, (uint32_t)(c4 >> 1)) + (c4 & 1) * 8;
            uint64_t hv = ((uint64_t)h2u(h23) << 32) | h2u(h01);
            uint64_t lv = ((uint64_t)h2u(l23) << 32) | h2u(l01);
            asm volatile("st.shared.b64 [%0], %1;" :: "r"(sb + T_AH + addr), "l"(hv) : "memory");
            asm volatile("st.shared.b64 [%0], %1;" :: "r"(sb + T_AL + addr), "l"(lv) : "memory");
        }
    };

    // pipeline prologue: stage 0
    LOADX(0);
    CPB(0, 0);
    CP_COMMIT();
    STSA(0);
    CP_WAIT0();
    __syncthreads();

    for (int kc = 0; kc < NUM_CHUNKS; kc++) {
        const bool more = (kc + 1 < NUM_CHUNKS);
        if (more) {
            LOADX(kc + 1);
            CPB(kc + 1, (kc + 1) & 1);
            CP_COMMIT();
        }

        const uint32_t sb = smem_base + OFF_TILES + (kc & 1) * STAGE_BYTES;
        const uint32_t sah = sb + T_AH, sal = sb + T_AL, sbh = sb + T_BH;

        #pragma unroll
        for (int ks = 0; ks < 4; ks++) {
            uint32_t ah0[4], ah1[4], al0[4], al1[4];
            LDMX4(ah0, sah + a_off[0][ks]);
            LDMX4(ah1, sah + a_off[1][ks]);
            LDMX4(al0, sal + a_off[0][ks]);
            LDMX4(al1, sal + a_off[1][ks]);
            uint32_t bh[2][4];
            LDMX4(bh[0], sbh + b_off[0][ks]);
            LDMX4(bh[1], sbh + b_off[1][ks]);
            #pragma unroll
            for (int g = 0; g < 2; g++) {
                #pragma unroll
                for (int h = 0; h < 2; h++) {
                    const int nb = g * 2 + h;
                    const uint32_t b0 = bh[g][2 * h], b1 = bh[g][2 * h + 1];
                    MMA_F16(acc[0][nb], ah0[0], ah0[1], ah0[2], ah0[3], b0, b1);
                    MMA_F16(acc[1][nb], ah1[0], ah1[1], ah1[2], ah1[3], b0, b1);
                    MMA_F16(acc[0][nb], al0[0], al0[1], al0[2], al0[3], b0, b1);
                    MMA_F16(acc[1][nb], al1[0], al1[1], al1[2], al1[3], b0, b1);
                }
            }
        }

        if (more) {
            STSA((kc + 1) & 1);
            CP_WAIT0();
            __syncthreads();
        }
    }

    // ---- epilogue: bias + mask-gated boundaries ----
    const float* sbias = (const float*)(smem + OFF_BIAS);
    const float* slb   = (const float*)(smem + OFF_LB);
    const float* srb   = (const float*)(smem + OFF_RB);
    const int gid = lid >> 2, tig = lid & 3;

    #pragma unroll
    for (int mb = 0; mb < 2; mb++) {
        #pragma unroll
        for (int p = 0; p < 2; p++) {
            int row = warp_m + mb * 16 + p * 8 + gid;
            int gm = blockIdx.x * M_TILE + row;
            int t = gm & (T_DIM - 1);
            int mc = mask[gm];
            int mp = (t > 0) ? mask[gm - 1] : 0;
            int mn = (t < T_DIM - 1) ? mask[gm + 1] : 0;
            float s = (mc > mp) ? 1.0f : 0.0f;
            float e = (mn > mc) ? 1.0f : 0.0f;
            float* orow = out + (size_t)gm * U_DIM;
            #pragma unroll
            for (int nb = 0; nb < 4; nb++) {
                int c = warp_n + nb * 8 + 2 * tig;
                float2 o;
                o.x = acc[mb][nb][2 * p + 0] + sbias[c + 0] + s * slb[c + 0] + e * srb[c + 0];
                o.y = acc[mb][nb][2 * p + 1] + sbias[c + 1] + s * slb[c + 1] + e * srb[c + 1];
                *reinterpret_cast<float2*>(orow + c) = o;
            }
        }
    }
}

extern "C" void kernel_launch(void* const* d_in, const int* in_sizes, int n_in,
                              void* d_out, int out_size) {
    const float* x    = (const float*)d_in[0];
    const int*   mask = (const int*)d_in[1];
    const float* kern = (const float*)d_in[2];
    const float* bias = (const float*)d_in[3];
    const float* lb   = (const float*)d_in[4];
    const float* rb   = (const float*)d_in[5];
    float* out = (float*)d_out;

    cudaFuncSetAttribute(crf_gemm_kernel,
                         cudaFuncAttributeMaxDynamicSharedMemorySize, SMEM_TOTAL);

    crf_bprep_kernel<<<(U_DIM * D_DIM) / 256, 256>>>(kern);
    crf_gemm_kernel<<<NUM_CTAS, THREADS, SMEM_TOTAL>>>(x, mask, bias, lb, rb, out);
}

// round 7
// speedup vs baseline: 1.9435x; 1.3495x over previous
#include <cuda_runtime.h>
#include <cuda_fp16.h>
#include <cstdint>

// Problem shape
#define B_DIM 64
#define T_DIM 512
#define D_DIM 1024
#define U_DIM 128
#define M_TOTAL (B_DIM * T_DIM)        // 32768
#define M_TILE  128
#define K_CHUNK 32
#define NUM_CHUNKS (D_DIM / K_CHUNK)   // 32
#define NUM_CTAS (M_TOTAL / M_TILE)    // 256
#define THREADS 256

// SMEM layout
#define OFF_BIAS  0
#define OFF_LB    512
#define OFF_RB    1024
#define OFF_TILES 1536
#define TILE_BYTES 8192                 // 128 rows x 64B (32 fp16)
#define STAGE_BYTES (2 * TILE_BYTES)    // A-hi, B-hi
#define T_AH 0
#define T_BH TILE_BYTES
#define SMEM_TOTAL (OFF_TILES + 2 * STAGE_BYTES)   // 34304

// Pre-converted B operand (kernel^T), K-major [U][D], fp16
__device__ __align__(16) __half g_Bh[U_DIM * D_DIM];

// ---------------- helpers ----------------
static __device__ __forceinline__ uint32_t smem_u32(const void* p) {
    uint32_t a;
    asm("{ .reg .u64 t; cvta.to.shared.u64 t, %1; cvt.u32.u64 %0, t; }" : "=r"(a) : "l"(p));
    return a;
}
static __device__ __forceinline__ uint32_t h2u(__half2 h) {
    return *reinterpret_cast<uint32_t*>(&h);
}
// swizzled byte offset of 16B chunk c (0..3) in row r of a 64B-wide tile
static __device__ __forceinline__ uint32_t swz(uint32_t r, uint32_t c) {
    return r * 64u + ((c ^ ((r >> 1) & 3u)) << 4);
}

#define LDMX4(R, addr) \
    asm volatile("ldmatrix.sync.aligned.m8n8.x4.shared.b16 {%0,%1,%2,%3}, [%4];" \
        : "=r"((R)[0]), "=r"((R)[1]), "=r"((R)[2]), "=r"((R)[3]) : "r"(addr))

#define MMA_F16(acc, A0, A1, A2, A3, B0, B1) \
    asm volatile("mma.sync.aligned.m16n8k16.row.col.f32.f16.f16.f32 " \
        "{%0,%1,%2,%3}, {%4,%5,%6,%7}, {%8,%9}, {%0,%1,%2,%3};" \
        : "+f"((acc)[0]), "+f"((acc)[1]), "+f"((acc)[2]), "+f"((acc)[3]) \
        : "r"(A0), "r"(A1), "r"(A2), "r"(A3), "r"(B0), "r"(B1))

#define CP_ASYNC16(dst, src) \
    asm volatile("cp.async.cg.shared.global [%0], [%1], 16;" \
                 :: "r"(dst), "l"(src) : "memory")
#define CP_COMMIT() asm volatile("cp.async.commit_group;" ::: "memory")
#define CP_WAIT0()  asm volatile("cp.async.wait_group 0;" ::: "memory")

// ---------------- Prologue: kernel[D,U] -> g_Bh [U,D] fp16 ----------------
__global__ void crf_bprep_kernel(const float* __restrict__ kern) {
    int e = blockIdx.x * blockDim.x + threadIdx.x;   // e = u*D + d
    int u = e >> 10;
    int d = e & (D_DIM - 1);
    g_Bh[e] = __float2half(kern[d * U_DIM + u]);
}

// ---------------- Main fused GEMM + boundary epilogue ----------------
__global__ __launch_bounds__(THREADS, 2) void crf_gemm_kernel(
    const float* __restrict__ x, const int* __restrict__ mask,
    const float* __restrict__ bias, const float* __restrict__ lb,
    const float* __restrict__ rb, float* __restrict__ out)
{
    extern __shared__ char smem[];
    const uint32_t smem_base = smem_u32(smem);
    const int tid = threadIdx.x;
    const int wid = tid >> 5;
    const int lid = tid & 31;
    const int warp_m = (wid & 3) * 32;   // 4 warps along M
    const int warp_n = (wid >> 2) * 64;  // 2 warps along N (m32 x n64 each)

    // stage bias / boundary vectors
    if (tid < U_DIM) {
        ((float*)(smem + OFF_BIAS))[tid] = bias[tid];
        ((float*)(smem + OFF_LB))[tid]   = lb[tid];
        ((float*)(smem + OFF_RB))[tid]   = rb[tid];
    }

    // per-lane ldmatrix offsets
    uint32_t a_off[2][2];   // [mb][ks]
    #pragma unroll
    for (int mb = 0; mb < 2; mb++)
        #pragma unroll
        for (int ks = 0; ks < 2; ks++) {
            uint32_t r = warp_m + mb * 16 + (lid & 15);
            uint32_t c = ks * 2 + (lid >> 4);
            a_off[mb][ks] = swz(r, c);
        }
    uint32_t b_off[4][2];   // [g][ks]
    #pragma unroll
    for (int g = 0; g < 4; g++)
        #pragma unroll
        for (int ks = 0; ks < 2; ks++) {
            uint32_t n = warp_n + g * 16 + (lid & 7) + ((lid >> 4) & 1) * 8;
            uint32_t c = ks * 2 + ((lid >> 3) & 1);
            b_off[g][ks] = swz(n, c);
        }

    const float* xblk = x + (size_t)blockIdx.x * (M_TILE * D_DIM);
    const __half* gbh = g_Bh;

    float acc[2][8][4];
    #pragma unroll
    for (int mb = 0; mb < 2; mb++)
        #pragma unroll
        for (int nb = 0; nb < 8; nb++)
            #pragma unroll
            for (int i = 0; i < 4; i++) acc[mb][nb][i] = 0.0f;

    float4 ax[4];

    auto LOADX = [&](int kc) {
        const int k0 = kc * K_CHUNK;
        #pragma unroll
        for (int j = 0; j < 4; j++) {
            int f = tid + THREADS * j;      // float4 index in 128x32 fp32 tile
            int r = f >> 3, c4 = f & 7;     // 8 float4 per row
            ax[j] = *reinterpret_cast<const float4*>(xblk + (size_t)r * D_DIM + k0 + c4 * 4);
        }
    };
    auto CPB = [&](int kc, int stage) {
        const uint32_t sb = smem_base + OFF_TILES + stage * STAGE_BYTES + T_BH;
        const int k0 = kc * K_CHUNK;
        #pragma unroll
        for (int j = 0; j < 2; j++) {
            int f = tid + THREADS * j;      // 16B chunk index in 128x64B tile
            int n = f >> 2, s = f & 3;      // 4 chunks per row
            CP_ASYNC16(sb + swz((uint32_t)n, (uint32_t)s),
                       gbh + (size_t)n * D_DIM + k0 + s * 8);
        }
    };
    auto STSA = [&](int stage) {
        const uint32_t sb = smem_base + OFF_TILES + stage * STAGE_BYTES + T_AH;
        #pragma unroll
        for (int j = 0; j < 4; j++) {
            int f = tid + THREADS * j;
            int r = f >> 3, c4 = f & 7;
            float4 v = ax[j];
            __half2 h01 = __float22half2_rn(make_float2(v.x, v.y));
            __half2 h23 = __float22half2_rn(make_float2(v.z, v.w));
            uint32_t addr = swz((uint32_t)r, (uint32_t)(c4 >> 1)) + (c4 & 1) * 8;
            uint64_t hv = ((uint64_t)h2u(h23) << 32) | h2u(h01);
            asm volatile("st.shared.b64 [%0], %1;" :: "r"(sb + addr), "l"(hv) : "memory");
        }
    };

    // pipeline prologue: stage 0
    LOADX(0);
    CPB(0, 0);
    CP_COMMIT();
    STSA(0);
    CP_WAIT0();
    __syncthreads();

    for (int kc = 0; kc < NUM_CHUNKS; kc++) {
        const bool more = (kc + 1 < NUM_CHUNKS);
        if (more) {
            LOADX(kc + 1);
            CPB(kc + 1, (kc + 1) & 1);
            CP_COMMIT();
        }

        const uint32_t sb = smem_base + OFF_TILES + (kc & 1) * STAGE_BYTES;
        const uint32_t sah = sb + T_AH, sbh = sb + T_BH;

        #pragma unroll
        for (int ks = 0; ks < 2; ks++) {
            uint32_t ah0[4], ah1[4];
            LDMX4(ah0, sah + a_off[0][ks]);
            LDMX4(ah1, sah + a_off[1][ks]);
            uint32_t bh[4][4];
            #pragma unroll
            for (int g = 0; g < 4; g++)
                LDMX4(bh[g], sbh + b_off[g][ks]);
            #pragma unroll
            for (int g = 0; g < 4; g++) {
                #pragma unroll
                for (int h = 0; h < 2; h++) {
                    const int nb = g * 2 + h;
                    const uint32_t b0 = bh[g][2 * h], b1 = bh[g][2 * h + 1];
                    MMA_F16(acc[0][nb], ah0[0], ah0[1], ah0[2], ah0[3], b0, b1);
                    MMA_F16(acc[1][nb], ah1[0], ah1[1], ah1[2], ah1[3], b0, b1);
                }
            }
        }

        if (more) {
            STSA((kc + 1) & 1);
            CP_WAIT0();
            __syncthreads();
        }
    }

    // ---- epilogue: bias + mask-gated boundaries ----
    const float* sbias = (const float*)(smem + OFF_BIAS);
    const float* slb   = (const float*)(smem + OFF_LB);
    const float* srb   = (const float*)(smem + OFF_RB);
    const int gid = lid >> 2, tig = lid & 3;

    #pragma unroll
    for (int mb = 0; mb < 2; mb++) {
        #pragma unroll
        for (int p = 0; p < 2; p++) {
            int row = warp_m + mb * 16 + p * 8 + gid;
            int gm = blockIdx.x * M_TILE + row;
            int t = gm & (T_DIM - 1);
            int mc = mask[gm];
            int mp = (t > 0) ? mask[gm - 1] : 0;
            int mn = (t < T_DIM - 1) ? mask[gm + 1] : 0;
            float s = (mc > mp) ? 1.0f : 0.0f;
            float e = (mn > mc) ? 1.0f : 0.0f;
            float* orow = out + (size_t)gm * U_DIM;
            #pragma unroll
            for (int nb = 0; nb < 8; nb++) {
                int c = warp_n + nb * 8 + 2 * tig;
                float2 o;
                o.x = acc[mb][nb][2 * p + 0] + sbias[c + 0] + s * slb[c + 0] + e * srb[c + 0];
                o.y = acc[mb][nb][2 * p + 1] + sbias[c + 1] + s * slb[c + 1] + e * srb[c + 1];
                *reinterpret_cast<float2*>(orow + c) = o;
            }
        }
    }
}

extern "C" void kernel_launch(void* const* d_in, const int* in_sizes, int n_in,
                              void* d_out, int out_size) {
    const float* x    = (const float*)d_in[0];
    const int*   mask = (const int*)d_in[1];
    const float* kern = (const float*)d_in[2];
    const float* bias = (const float*)d_in[3];
    const float* lb   = (const float*)d_in[4];
    const float* rb   = (const float*)d_in[5];
    float* out = (float*)d_out;

    cudaFuncSetAttribute(crf_gemm_kernel,
                         cudaFuncAttributeMaxDynamicSharedMemorySize, SMEM_TOTAL);

    crf_bprep_kernel<<<(U_DIM * D_DIM) / 256, 256>>>(kern);
    crf_gemm_kernel<<<NUM_CTAS, THREADS, SMEM_TOTAL>>>(x, mask, bias, lb, rb, out);
}